// round 2
// baseline (speedup 1.0000x reference)
#include <cuda_runtime.h>
#include <math.h>
#include <float.h>

#define NN 100000
#define EE 1600000
#define FH 64
#define FO 40

// ---------------- static scratch (no allocations allowed) ----------------
__device__ int   g_deg[NN];
__device__ int   g_row_ptr[NN + 1];
__device__ int   g_cursor[NN];
__device__ int   g_csr[EE];
__device__ float g_inv_deg[NN];
__device__ float g_agg[(size_t)NN * FH];
__device__ float g_h1[(size_t)NN * FH];
__device__ float g_h2[(size_t)NN * FH];

// ---------------- graph preprocessing ----------------
__global__ void k_zero_deg() {
    int i = blockIdx.x * blockDim.x + threadIdx.x;
    if (i < NN) g_deg[i] = 0;
}

__global__ void k_degree(const int* __restrict__ er) {
    int e = blockIdx.x * blockDim.x + threadIdx.x;
    if (e < EE) atomicAdd(&g_deg[er[e]], 1);
}

// single-block exclusive scan of deg -> row_ptr / cursor / inv_deg
__global__ void k_scan() {
    __shared__ int sm[1024];
    const int CHUNK = (NN + 1023) / 1024;  // 98
    int t = threadIdx.x;
    int start = t * CHUNK;
    int end = start + CHUNK; if (end > NN) end = NN;
    int s = 0;
    for (int i = start; i < end; i++) s += g_deg[i];
    sm[t] = s;
    __syncthreads();
    for (int o = 1; o < 1024; o <<= 1) {
        int v = (t >= o) ? sm[t - o] : 0;
        __syncthreads();
        sm[t] += v;
        __syncthreads();
    }
    int off = sm[t] - s;  // exclusive prefix
    for (int i = start; i < end; i++) {
        int d = g_deg[i];
        g_row_ptr[i] = off;
        g_cursor[i]  = off;
        g_inv_deg[i] = (d > 0) ? (1.0f / (float)d) : 0.0f;
        off += d;
    }
    if (t == 1023) g_row_ptr[NN] = sm[1023];
}

__global__ void k_fill(const int* __restrict__ er, const int* __restrict__ ec) {
    int e = blockIdx.x * blockDim.x + threadIdx.x;
    if (e >= EE) return;
    int r = er[e];
    int p = atomicAdd(&g_cursor[r], 1);
    g_csr[p] = ec[e];
}

// ---------------- aggregation: warp per node, mean over CSR neighbors ----------------
__global__ __launch_bounds__(256) void k_agg(const float* __restrict__ act,
                                             float* __restrict__ agg) {
    int w    = (blockIdx.x * blockDim.x + threadIdx.x) >> 5;
    int lane = threadIdx.x & 31;
    if (w >= NN) return;
    int s = g_row_ptr[w];
    int e = g_row_ptr[w + 1];
    float ax = 0.f, ay = 0.f, bx = 0.f, by = 0.f;
    int i = s;
    for (; i + 1 < e; i += 2) {
        int j0 = g_csr[i], j1 = g_csr[i + 1];
        float2 v0 = *(const float2*)(act + (size_t)j0 * FH + lane * 2);
        float2 v1 = *(const float2*)(act + (size_t)j1 * FH + lane * 2);
        ax += v0.x; ay += v0.y;
        bx += v1.x; by += v1.y;
    }
    if (i < e) {
        int j0 = g_csr[i];
        float2 v0 = *(const float2*)(act + (size_t)j0 * FH + lane * 2);
        ax += v0.x; ay += v0.y;
    }
    float d = g_inv_deg[w];
    float2 r;
    r.x = (ax + bx) * d;
    r.y = (ay + by) * d;
    *(float2*)(agg + (size_t)w * FH + lane * 2) = r;
}

// ---------------- GEMM: out = A1@W1 + A2@W2 + (b1+b2), optional relu ----------------
// A1, A2: N x 64.  W: 64 x Fo (row-major). out: N x Fo.
// Block: BM=128 rows x 64 cols (cols >= Fo masked). 256 threads, TM=8 x TN=4.
// smem: sW 16KB + sA 32KB = 48KB exactly (static limit).
__global__ __launch_bounds__(256) void k_gemm(const float* __restrict__ A1,
                                              const float* __restrict__ A2,
                                              const float* __restrict__ W1,
                                              const float* __restrict__ b1,
                                              const float* __restrict__ W2,
                                              const float* __restrict__ b2,
                                              float* __restrict__ out,
                                              int Fo, int doRelu) {
    __shared__ float sW[64][64];
    __shared__ float sA[128][64];

    int tid = threadIdx.x;
    int tx = tid & 15;   // col group: cols tx*4 .. tx*4+3
    int ty = tid >> 4;   // row group: rows ty*8 .. ty*8+7
    int row0 = blockIdx.x * 128;

    float acc[8][4];
#pragma unroll
    for (int i = 0; i < 8; i++)
#pragma unroll
        for (int j = 0; j < 4; j++) acc[i][j] = 0.f;

    for (int pass = 0; pass < 2; ++pass) {
        const float* A = pass ? A2 : A1;
        const float* W = pass ? W2 : W1;
        if (pass) __syncthreads();  // protect smem from previous pass
        // load W (64 x Fo) into sW, zero-padded to 64 cols
        for (int i = tid; i < 64 * 16; i += 256) {
            int r = i >> 4, c4 = (i & 15) * 4;
            float4 v = {0.f, 0.f, 0.f, 0.f};
            if (c4 + 3 < Fo) v = *(const float4*)(W + (size_t)r * Fo + c4);
            *(float4*)&sW[r][c4] = v;
        }
        // load A tile (128 x 64)
        for (int i = tid; i < 128 * 16; i += 256) {
            int r = i >> 4, c4 = (i & 15) * 4;
            int gr = row0 + r;
            float4 v = {0.f, 0.f, 0.f, 0.f};
            if (gr < NN) v = *(const float4*)(A + (size_t)gr * FH + c4);
            *(float4*)&sA[r][c4] = v;
        }
        __syncthreads();
#pragma unroll 4
        for (int k = 0; k < 64; ++k) {
            float4 w = *(const float4*)&sW[k][tx * 4];
#pragma unroll
            for (int i = 0; i < 8; ++i) {
                float a = sA[ty * 8 + i][k];
                acc[i][0] = fmaf(a, w.x, acc[i][0]);
                acc[i][1] = fmaf(a, w.y, acc[i][1]);
                acc[i][2] = fmaf(a, w.z, acc[i][2]);
                acc[i][3] = fmaf(a, w.w, acc[i][3]);
            }
        }
    }
    // epilogue: bias from global (L1-cached), optional relu
    int c = tx * 4;
    if (c < Fo) {
        float bb0 = b1[c + 0] + b2[c + 0];
        float bb1 = b1[c + 1] + b2[c + 1];
        float bb2 = b1[c + 2] + b2[c + 2];
        float bb3 = b1[c + 3] + b2[c + 3];
#pragma unroll
        for (int i = 0; i < 8; ++i) {
            int r = row0 + ty * 8 + i;
            if (r < NN) {
                float4 v;
                v.x = acc[i][0] + bb0;
                v.y = acc[i][1] + bb1;
                v.z = acc[i][2] + bb2;
                v.w = acc[i][3] + bb3;
                if (doRelu) {
                    v.x = fmaxf(v.x, 0.f); v.y = fmaxf(v.y, 0.f);
                    v.z = fmaxf(v.z, 0.f); v.w = fmaxf(v.w, 0.f);
                }
                *(float4*)(out + (size_t)r * Fo + c) = v;
            }
        }
    }
}

// ---------------- log-softmax over 40 features, warp per row, in place ----------------
__global__ __launch_bounds__(256) void k_lsm(float* __restrict__ out) {
    int w    = (blockIdx.x * blockDim.x + threadIdx.x) >> 5;
    int lane = threadIdx.x & 31;
    if (w >= NN) return;
    float* p = out + (size_t)w * FO;
    float v0 = p[lane];
    float v1 = (lane < FO - 32) ? p[32 + lane] : -FLT_MAX;
    float m = fmaxf(v0, v1);
#pragma unroll
    for (int o = 16; o > 0; o >>= 1) m = fmaxf(m, __shfl_xor_sync(0xFFFFFFFFu, m, o));
    float s = __expf(v0 - m) + ((lane < FO - 32) ? __expf(v1 - m) : 0.f);
#pragma unroll
    for (int o = 16; o > 0; o >>= 1) s += __shfl_xor_sync(0xFFFFFFFFu, s, o);
    float ls = m + logf(s);
    p[lane] = v0 - ls;
    if (lane < FO - 32) p[32 + lane] = v1 - ls;
}

// ---------------- launch ----------------
extern "C" void kernel_launch(void* const* d_in, const int* in_sizes, int n_in,
                              void* d_out, int out_size) {
    const float* x   = (const float*)d_in[0];
    const int*   er  = (const int*)d_in[1];
    const int*   ec  = (const int*)d_in[2];
    const float* Wl0 = (const float*)d_in[5];
    const float* bl0 = (const float*)d_in[6];
    const float* Wr0 = (const float*)d_in[7];
    const float* br0 = (const float*)d_in[8];
    const float* Wl1 = (const float*)d_in[9];
    const float* bl1 = (const float*)d_in[10];
    const float* Wr1 = (const float*)d_in[11];
    const float* br1 = (const float*)d_in[12];
    const float* Wl2 = (const float*)d_in[13];
    const float* bl2 = (const float*)d_in[14];
    const float* Wr2 = (const float*)d_in[15];
    const float* br2 = (const float*)d_in[16];
    float* out = (float*)d_out;

    float* agg; cudaGetSymbolAddress((void**)&agg, g_agg);
    float* h1;  cudaGetSymbolAddress((void**)&h1,  g_h1);
    float* h2;  cudaGetSymbolAddress((void**)&h2,  g_h2);

    // graph preprocessing (rebuilt every replay; fully overwritten -> idempotent)
    k_zero_deg<<<(NN + 1023) / 1024, 1024>>>();
    k_degree<<<(EE + 255) / 256, 256>>>(er);
    k_scan<<<1, 1024>>>();
    k_fill<<<(EE + 255) / 256, 256>>>(er, ec);

    const int AGG_BLOCKS  = (NN + 7) / 8;        // 8 warps per 256-thread block
    const int GEMM_BLOCKS = (NN + 127) / 128;

    // layer 0
    k_agg<<<AGG_BLOCKS, 256>>>(x, agg);
    k_gemm<<<GEMM_BLOCKS, 256>>>(agg, x, Wl0, bl0, Wr0, br0, h1, FH, 1);
    // layer 1
    k_agg<<<AGG_BLOCKS, 256>>>(h1, agg);
    k_gemm<<<GEMM_BLOCKS, 256>>>(agg, h1, Wl1, bl1, Wr1, br1, h2, FH, 1);
    // layer 2 (no relu, Fo=40) -> logits straight into d_out
    k_agg<<<AGG_BLOCKS, 256>>>(h2, agg);
    k_gemm<<<GEMM_BLOCKS, 256>>>(agg, h2, Wl2, bl2, Wr2, br2, out, FO, 0);

    k_lsm<<<(NN * 32 + 255) / 256, 256>>>(out);
}